// round 1
// baseline (speedup 1.0000x reference)
#include <cuda_runtime.h>

#define NN 50000
#define NE 800000
#define CIN 128
#define CH 64

// ---------------- scratch (no allocs allowed -> device globals) ----------------
__device__ float g_deg[NN];
__device__ float g_dis[NN];
__device__ int   g_src[NE];
__device__ int   g_dst[NE];
__device__ float g_norm[NE];
__device__ float g_h1[(size_t)NN * CH];
__device__ float g_acc1[(size_t)NN * CH];
__device__ float g_h2[(size_t)NN * CH];
__device__ int   g_is64;

// ---------------- index dtype detection (int64 vs int32) ----------------
// If the buffer is int32, reading it as int64 packs two node ids per word ->
// values are astronomically out of [0, NN) range with overwhelming probability.
__global__ void k_detect(const long long* __restrict__ idx) {
    if (blockIdx.x == 0 && threadIdx.x == 0) {
        int ok = 1;
        #pragma unroll
        for (int i = 0; i < 32; i++) {
            long long v = idx[i];
            if (v < 0 || v >= NN) ok = 0;
        }
        g_is64 = ok;
    }
}

__global__ void k_deg_init() {
    int i = blockIdx.x * blockDim.x + threadIdx.x;
    if (i < NN) g_deg[i] = 1.0f;  // self-loop contributes 1
}

// convert indices to int32 scratch + accumulate degree at dst
__global__ void k_prep(const void* __restrict__ idx) {
    int e = blockIdx.x * blockDim.x + threadIdx.x;
    if (e >= NE) return;
    int s, d;
    if (g_is64) {
        const long long* p = (const long long*)idx;
        s = (int)p[e];
        d = (int)p[NE + e];
    } else {
        const int* p = (const int*)idx;
        s = p[e];
        d = p[NE + e];
    }
    g_src[e] = s;
    g_dst[e] = d;
    atomicAdd(&g_deg[d], 1.0f);
}

__global__ void k_dis() {
    int i = blockIdx.x * blockDim.x + threadIdx.x;
    if (i < NN) g_dis[i] = rsqrtf(g_deg[i]);
}

__global__ void k_norm() {
    int e = blockIdx.x * blockDim.x + threadIdx.x;
    if (e < NE) g_norm[e] = g_dis[g_src[e]] * g_dis[g_dst[e]];
}

// ---------------- GEMM1: h1 = x @ W1 ; acc1 = dis^2 * h1 + b1 ----------------
// Block: 64 rows x 64 cols, 128 threads, 4x8 register tile per thread.
// Xs padded to stride 130 (130 % 8 == 2 -> 4-row scalar reads hit distinct banks).
__global__ __launch_bounds__(128) void k_gemm1(const float* __restrict__ x,
                                               const float* __restrict__ W,
                                               const float* __restrict__ b) {
    extern __shared__ float sm[];
    float* Ws = sm;             // 128*64
    float* Xs = sm + CIN * CH;  // 64*130
    const int t = threadIdx.x;
    const int row0 = blockIdx.x * 64;

    {
        const float4* Wg = (const float4*)W;
        float4* Wsv = (float4*)Ws;
        #pragma unroll
        for (int i = 0; i < 16; i++) Wsv[i * 128 + t] = Wg[i * 128 + t];
    }
    #pragma unroll
    for (int i = 0; i < 64; i++) {
        int e = i * 128 + t;
        int r = e >> 7, c = e & 127;
        int gr = row0 + r;
        Xs[r * 130 + c] = (gr < NN) ? __ldg(x + (size_t)gr * CIN + c) : 0.0f;
    }
    __syncthreads();

    const int tx = t & 7;   // 8 col tiles of 8 cols
    const int ty = t >> 3;  // 16 row tiles of 4 rows
    const float* Xp = Xs + ty * 4 * 130;
    float acc[4][8];
    #pragma unroll
    for (int r = 0; r < 4; r++)
        #pragma unroll
        for (int c = 0; c < 8; c++) acc[r][c] = 0.0f;

    #pragma unroll 4
    for (int k = 0; k < CIN; k++) {
        float wr[8];
        *(float4*)(wr)     = *(const float4*)(Ws + k * CH + tx * 8);
        *(float4*)(wr + 4) = *(const float4*)(Ws + k * CH + tx * 8 + 4);
        float xr[4];
        xr[0] = Xp[k];
        xr[1] = Xp[130 + k];
        xr[2] = Xp[260 + k];
        xr[3] = Xp[390 + k];
        #pragma unroll
        for (int r = 0; r < 4; r++)
            #pragma unroll
            for (int c = 0; c < 8; c++) acc[r][c] += xr[r] * wr[c];
    }

    float4 bv0 = __ldg((const float4*)b + tx * 2);
    float4 bv1 = __ldg((const float4*)b + tx * 2 + 1);
    #pragma unroll
    for (int r = 0; r < 4; r++) {
        int gr = row0 + ty * 4 + r;
        if (gr < NN) {
            float ds = g_dis[gr];
            float d2 = ds * ds;
            float* hp = g_h1 + (size_t)gr * CH + tx * 8;
            float* ap = g_acc1 + (size_t)gr * CH + tx * 8;
            float4 h0 = make_float4(acc[r][0], acc[r][1], acc[r][2], acc[r][3]);
            float4 h1 = make_float4(acc[r][4], acc[r][5], acc[r][6], acc[r][7]);
            *(float4*)hp = h0;
            *(float4*)(hp + 4) = h1;
            float4 a0 = make_float4(h0.x * d2 + bv0.x, h0.y * d2 + bv0.y,
                                    h0.z * d2 + bv0.z, h0.w * d2 + bv0.w);
            float4 a1 = make_float4(h1.x * d2 + bv1.x, h1.y * d2 + bv1.y,
                                    h1.z * d2 + bv1.z, h1.w * d2 + bv1.w);
            *(float4*)ap = a0;
            *(float4*)(ap + 4) = a1;
        }
    }
}

// ---------------- GEMM2: h2 = relu(acc1) @ W2 ; out = dis^2 * h2 + b2 ----------------
__global__ __launch_bounds__(128) void k_gemm2(const float* __restrict__ W,
                                               const float* __restrict__ b,
                                               float* __restrict__ out) {
    __shared__ float Ws[CH * CH];  // 4096
    __shared__ float Xs[64 * 66];  // stride 66 (66 % 8 == 2)
    const int t = threadIdx.x;
    const int row0 = blockIdx.x * 64;

    {
        const float4* Wg = (const float4*)W;
        float4* Wsv = (float4*)Ws;
        #pragma unroll
        for (int i = 0; i < 8; i++) Wsv[i * 128 + t] = Wg[i * 128 + t];
    }
    #pragma unroll
    for (int i = 0; i < 32; i++) {
        int e = i * 128 + t;
        int r = e >> 6, c = e & 63;
        int gr = row0 + r;
        float v = (gr < NN) ? g_acc1[(size_t)gr * CH + c] : 0.0f;
        Xs[r * 66 + c] = fmaxf(v, 0.0f);  // fused ReLU (bias b1 already inside acc1)
    }
    __syncthreads();

    const int tx = t & 7;
    const int ty = t >> 3;
    const float* Xp = Xs + ty * 4 * 66;
    float acc[4][8];
    #pragma unroll
    for (int r = 0; r < 4; r++)
        #pragma unroll
        for (int c = 0; c < 8; c++) acc[r][c] = 0.0f;

    #pragma unroll 4
    for (int k = 0; k < CH; k++) {
        float wr[8];
        *(float4*)(wr)     = *(const float4*)(Ws + k * CH + tx * 8);
        *(float4*)(wr + 4) = *(const float4*)(Ws + k * CH + tx * 8 + 4);
        float xr[4];
        xr[0] = Xp[k];
        xr[1] = Xp[66 + k];
        xr[2] = Xp[132 + k];
        xr[3] = Xp[198 + k];
        #pragma unroll
        for (int r = 0; r < 4; r++)
            #pragma unroll
            for (int c = 0; c < 8; c++) acc[r][c] += xr[r] * wr[c];
    }

    float4 bv0 = __ldg((const float4*)b + tx * 2);
    float4 bv1 = __ldg((const float4*)b + tx * 2 + 1);
    #pragma unroll
    for (int r = 0; r < 4; r++) {
        int gr = row0 + ty * 4 + r;
        if (gr < NN) {
            float ds = g_dis[gr];
            float d2 = ds * ds;
            float* hp = g_h2 + (size_t)gr * CH + tx * 8;
            float* op = out + (size_t)gr * CH + tx * 8;
            float4 h0 = make_float4(acc[r][0], acc[r][1], acc[r][2], acc[r][3]);
            float4 h1 = make_float4(acc[r][4], acc[r][5], acc[r][6], acc[r][7]);
            *(float4*)hp = h0;
            *(float4*)(hp + 4) = h1;
            float4 a0 = make_float4(h0.x * d2 + bv0.x, h0.y * d2 + bv0.y,
                                    h0.z * d2 + bv0.z, h0.w * d2 + bv0.w);
            float4 a1 = make_float4(h1.x * d2 + bv1.x, h1.y * d2 + bv1.y,
                                    h1.z * d2 + bv1.z, h1.w * d2 + bv1.w);
            *(float4*)op = a0;
            *(float4*)(op + 4) = a1;
        }
    }
}

// ---------------- edge scatter: acc[dst] += norm * h[src], vector atomics ----------------
// 16 threads per edge, one float4 (16B) red.global each -> 12.8M vector atomics.
template <int L>
__global__ __launch_bounds__(256) void k_scatter(float* __restrict__ out) {
    int idx = blockIdx.x * blockDim.x + threadIdx.x;
    if (idx >= NE * 16) return;
    int e = idx >> 4;
    int q = idx & 15;
    const float* h = (L == 1) ? g_h1 : g_h2;
    float* acc = (L == 1) ? g_acc1 : out;
    int s = g_src[e];
    int d = g_dst[e];
    float nm = g_norm[e];
    float4 v = __ldg((const float4*)(h + (size_t)s * CH) + q);
    float* p = acc + (size_t)d * CH + (q << 2);
    asm volatile("red.global.add.v4.f32 [%0], {%1, %2, %3, %4};" ::"l"(p),
                 "f"(v.x * nm), "f"(v.y * nm), "f"(v.z * nm), "f"(v.w * nm)
                 : "memory");
}

// ---------------- launch ----------------
extern "C" void kernel_launch(void* const* d_in, const int* in_sizes, int n_in,
                              void* d_out, int out_size) {
    const float* x  = (const float*)d_in[0];
    const void*  ei = d_in[1];
    const float* W1 = (const float*)d_in[2];
    const float* b1 = (const float*)d_in[3];
    const float* W2 = (const float*)d_in[4];
    const float* b2 = (const float*)d_in[5];
    float* out = (float*)d_out;

    const int gemm1_smem = (CIN * CH + 64 * 130) * (int)sizeof(float);  // ~64.5 KB
    cudaFuncSetAttribute(k_gemm1, cudaFuncAttributeMaxDynamicSharedMemorySize,
                         gemm1_smem);

    k_detect<<<1, 32>>>((const long long*)ei);
    k_deg_init<<<(NN + 255) / 256, 256>>>();
    k_prep<<<NE / 256, 256>>>(ei);
    k_dis<<<(NN + 255) / 256, 256>>>();
    k_norm<<<NE / 256, 256>>>();
    k_gemm1<<<(NN + 63) / 64, 128, gemm1_smem>>>(x, W1, b1);
    k_scatter<1><<<(NE * 16) / 256, 256>>>(nullptr);
    k_gemm2<<<(NN + 63) / 64, 128>>>(W2, b2, out);
    k_scatter<2><<<(NE * 16) / 256, 256>>>(out);
}

// round 5
// speedup vs baseline: 1.3341x; 1.3341x over previous
#include <cuda_runtime.h>

#define NN 50000
#define NE 800000
#define CIN 128
#define CH 64
#define NB 196  // ceil(NN/256); 196*256 = 50176 > NN, so i==NN exists in-grid

// ---------------- scratch (no allocs allowed -> device globals) ----------------
__device__ int   g_cnt[NN];        // in-degree (dst) histogram
__device__ int   g_off[NN + 1];    // CSR offsets
__device__ int   g_cur[NN];        // reorder cursors
__device__ float g_dis[NN];        // rsqrt(deg+1)
__device__ int   g_src[NE];
__device__ int   g_dst[NE];
__device__ int   g_eidx[NE];       // dst-sorted src indices (CSR adjacency)
__device__ int   g_psum[NB];       // per-block count sums
__device__ int   g_poff[NB];       // per-block exclusive offsets
__device__ float g_h1[(size_t)NN * CH];   // dis[i] * (x @ W1)
__device__ float g_acc1[(size_t)NN * CH]; // layer-1 output (post-bias, pre-ReLU)
__device__ float g_h2[(size_t)NN * CH];   // dis[i] * (relu(acc1) @ W2)
__device__ int   g_is64;

// ---------------- init: zero histogram + index-dtype detect ----------------
__global__ __launch_bounds__(256) void k_init(const long long* __restrict__ idx) {
    int i = blockIdx.x * blockDim.x + threadIdx.x;
    if (i < NN) g_cnt[i] = 0;
    if (i == 0) {
        int ok = 1;
        for (int j = 0; j < 16; j++) {
            long long v = idx[j];
            if (v < 0 || v >= NN) ok = 0;
        }
        g_is64 = ok;
    }
}

// ---------------- convert indices + in-degree histogram ----------------
__global__ __launch_bounds__(256) void k_deg(const void* __restrict__ idx) {
    int e = blockIdx.x * blockDim.x + threadIdx.x;
    if (e >= NE) return;
    int s, d;
    if (g_is64) {
        const long long* p = (const long long*)idx;
        s = (int)p[e];
        d = (int)p[NE + e];
    } else {
        const int* p = (const int*)idx;
        s = p[e];
        d = p[NE + e];
    }
    g_src[e] = s;
    g_dst[e] = d;
    atomicAdd(&g_cnt[d], 1);
}

// ---------------- scan stage 1: per-block sum of 256 counts ----------------
__global__ __launch_bounds__(256) void k_part() {
    __shared__ int sm[256];
    const int t = threadIdx.x;
    int i = blockIdx.x * 256 + t;
    sm[t] = (i < NN) ? g_cnt[i] : 0;
    __syncthreads();
    for (int o = 128; o > 0; o >>= 1) {
        if (t < o) sm[t] += sm[t + o];
        __syncthreads();
    }
    if (t == 0) g_psum[blockIdx.x] = sm[0];
}

// ---------------- scan stage 2: 1-block exclusive scan of NB partials ----------------
__global__ __launch_bounds__(256) void k_pscan() {
    __shared__ int sm[256];
    const int t = threadIdx.x;
    int v = (t < NB) ? g_psum[t] : 0;
    sm[t] = v;
    __syncthreads();
    for (int o = 1; o < 256; o <<= 1) {
        int u = (t >= o) ? sm[t - o] : 0;
        __syncthreads();
        sm[t] += u;
        __syncthreads();
    }
    if (t < NB) g_poff[t] = sm[t] - v;  // exclusive
}

// ---------------- scan stage 3: block-local scan + write offsets/cursors/dis ----------------
__global__ __launch_bounds__(256) void k_off() {
    __shared__ int sm[256];
    const int t = threadIdx.x;
    int i = blockIdx.x * 256 + t;
    int c = (i < NN) ? g_cnt[i] : 0;
    sm[t] = c;
    __syncthreads();
    for (int o = 1; o < 256; o <<= 1) {
        int u = (t >= o) ? sm[t - o] : 0;
        __syncthreads();
        sm[t] += u;
        __syncthreads();
    }
    int off = g_poff[blockIdx.x] + sm[t] - c;  // block base + in-block exclusive
    if (i < NN) {
        g_off[i] = off;
        g_cur[i] = off;
        g_dis[i] = rsqrtf((float)(c + 1));  // degree includes self-loop
    }
    if (i == NN) g_off[NN] = off;  // == NE
}

// ---------------- reorder: pure permutation into dst-sorted adjacency ----------------
__global__ __launch_bounds__(256) void k_reorder() {
    int e = blockIdx.x * blockDim.x + threadIdx.x;
    if (e >= NE) return;
    int d = g_dst[e];
    int pos = atomicAdd(&g_cur[d], 1);
    g_eidx[pos] = g_src[e];
}

// ---------------- GEMM1: h1 = dis[row] * (x @ W1) ----------------
__global__ __launch_bounds__(128) void k_gemm1(const float* __restrict__ x,
                                               const float* __restrict__ W) {
    extern __shared__ float sm[];
    float* Ws = sm;             // 128*64
    float* Xs = sm + CIN * CH;  // 64*130
    const int t = threadIdx.x;
    const int row0 = blockIdx.x * 64;

    {
        const float4* Wg = (const float4*)W;
        float4* Wsv = (float4*)Ws;
        #pragma unroll
        for (int i = 0; i < 16; i++) Wsv[i * 128 + t] = Wg[i * 128 + t];
    }
    #pragma unroll
    for (int i = 0; i < 64; i++) {
        int e = i * 128 + t;
        int r = e >> 7, c = e & 127;
        int gr = row0 + r;
        Xs[r * 130 + c] = (gr < NN) ? __ldg(x + (size_t)gr * CIN + c) : 0.0f;
    }
    __syncthreads();

    const int tx = t & 7;
    const int ty = t >> 3;
    const float* Xp = Xs + ty * 4 * 130;
    float acc[4][8];
    #pragma unroll
    for (int r = 0; r < 4; r++)
        #pragma unroll
        for (int c = 0; c < 8; c++) acc[r][c] = 0.0f;

    #pragma unroll 4
    for (int k = 0; k < CIN; k++) {
        float wr[8];
        *(float4*)(wr)     = *(const float4*)(Ws + k * CH + tx * 8);
        *(float4*)(wr + 4) = *(const float4*)(Ws + k * CH + tx * 8 + 4);
        float xr[4];
        xr[0] = Xp[k];
        xr[1] = Xp[130 + k];
        xr[2] = Xp[260 + k];
        xr[3] = Xp[390 + k];
        #pragma unroll
        for (int r = 0; r < 4; r++)
            #pragma unroll
            for (int c = 0; c < 8; c++) acc[r][c] += xr[r] * wr[c];
    }

    #pragma unroll
    for (int r = 0; r < 4; r++) {
        int gr = row0 + ty * 4 + r;
        if (gr < NN) {
            float ds = g_dis[gr];
            float* hp = g_h1 + (size_t)gr * CH + tx * 8;
            *(float4*)hp = make_float4(ds * acc[r][0], ds * acc[r][1],
                                       ds * acc[r][2], ds * acc[r][3]);
            *(float4*)(hp + 4) = make_float4(ds * acc[r][4], ds * acc[r][5],
                                             ds * acc[r][6], ds * acc[r][7]);
        }
    }
}

// ---------------- GEMM2: h2 = dis[row] * (relu(acc1) @ W2) ----------------
__global__ __launch_bounds__(128) void k_gemm2(const float* __restrict__ W) {
    __shared__ float Ws[CH * CH];
    __shared__ float Xs[64 * 66];
    const int t = threadIdx.x;
    const int row0 = blockIdx.x * 64;

    {
        const float4* Wg = (const float4*)W;
        float4* Wsv = (float4*)Ws;
        #pragma unroll
        for (int i = 0; i < 8; i++) Wsv[i * 128 + t] = Wg[i * 128 + t];
    }
    #pragma unroll
    for (int i = 0; i < 32; i++) {
        int e = i * 128 + t;
        int r = e >> 6, c = e & 63;
        int gr = row0 + r;
        float v = (gr < NN) ? g_acc1[(size_t)gr * CH + c] : 0.0f;
        Xs[r * 66 + c] = fmaxf(v, 0.0f);  // fused ReLU
    }
    __syncthreads();

    const int tx = t & 7;
    const int ty = t >> 3;
    const float* Xp = Xs + ty * 4 * 66;
    float acc[4][8];
    #pragma unroll
    for (int r = 0; r < 4; r++)
        #pragma unroll
        for (int c = 0; c < 8; c++) acc[r][c] = 0.0f;

    #pragma unroll 4
    for (int k = 0; k < CH; k++) {
        float wr[8];
        *(float4*)(wr)     = *(const float4*)(Ws + k * CH + tx * 8);
        *(float4*)(wr + 4) = *(const float4*)(Ws + k * CH + tx * 8 + 4);
        float xr[4];
        xr[0] = Xp[k];
        xr[1] = Xp[66 + k];
        xr[2] = Xp[132 + k];
        xr[3] = Xp[198 + k];
        #pragma unroll
        for (int r = 0; r < 4; r++)
            #pragma unroll
            for (int c = 0; c < 8; c++) acc[r][c] += xr[r] * wr[c];
    }

    #pragma unroll
    for (int r = 0; r < 4; r++) {
        int gr = row0 + ty * 4 + r;
        if (gr < NN) {
            float ds = g_dis[gr];
            float* hp = g_h2 + (size_t)gr * CH + tx * 8;
            *(float4*)hp = make_float4(ds * acc[r][0], ds * acc[r][1],
                                       ds * acc[r][2], ds * acc[r][3]);
            *(float4*)(hp + 4) = make_float4(ds * acc[r][4], ds * acc[r][5],
                                             ds * acc[r][6], ds * acc[r][7]);
        }
    }
}

// ---------------- CSR gather: dst[i] = dis[i]*(hs[i] + sum_e hs[src_e]) + b ----------------
// One warp per node; each lane owns 2 columns (float2). Destination selected
// INSIDE device code (never pass a __device__ symbol as a host-side kernel arg
// -- that passes the host shadow address and trips the memory guard).
template <int L>
__global__ __launch_bounds__(256) void k_gather(const float* __restrict__ b,
                                                float* __restrict__ out_arg) {
    const int node = blockIdx.x * 8 + (threadIdx.x >> 5);
    const int lane = threadIdx.x & 31;
    if (node >= NN) return;
    const float* __restrict__ hs = (L == 1) ? g_h1 : g_h2;
    float* __restrict__ dst = (L == 1) ? g_acc1 : out_arg;

    float2 acc = __ldg((const float2*)(hs + (size_t)node * CH) + lane);  // self term

    const int s0 = g_off[node];
    const int s1 = g_off[node + 1];
    for (int e = s0; e < s1; e++) {
        int sj = __ldg(g_eidx + e);
        float2 v = __ldg((const float2*)(hs + (size_t)sj * CH) + lane);
        acc.x += v.x;
        acc.y += v.y;
    }

    float ds = g_dis[node];
    float2 bv = __ldg((const float2*)b + lane);
    float2 o;
    o.x = ds * acc.x + bv.x;
    o.y = ds * acc.y + bv.y;
    *((float2*)(dst + (size_t)node * CH) + lane) = o;
}

// ---------------- launch ----------------
extern "C" void kernel_launch(void* const* d_in, const int* in_sizes, int n_in,
                              void* d_out, int out_size) {
    const float* x  = (const float*)d_in[0];
    const void*  ei = d_in[1];
    const float* W1 = (const float*)d_in[2];
    const float* b1 = (const float*)d_in[3];
    const float* W2 = (const float*)d_in[4];
    const float* b2 = (const float*)d_in[5];
    float* out = (float*)d_out;

    const int gemm1_smem = (CIN * CH + 64 * 130) * (int)sizeof(float);
    cudaFuncSetAttribute(k_gemm1, cudaFuncAttributeMaxDynamicSharedMemorySize,
                         gemm1_smem);

    k_init<<<NB, 256>>>((const long long*)ei);
    k_deg<<<NE / 256, 256>>>(ei);
    k_part<<<NB, 256>>>();
    k_pscan<<<1, 256>>>();
    k_off<<<NB, 256>>>();
    k_reorder<<<NE / 256, 256>>>();
    k_gemm1<<<(NN + 63) / 64, 128, gemm1_smem>>>(x, W1);
    k_gather<1><<<(NN + 7) / 8, 256>>>(b1, nullptr);
    k_gemm2<<<(NN + 63) / 64, 128>>>(W2);
    k_gather<2><<<(NN + 7) / 8, 256>>>(b2, out);
}

// round 6
// speedup vs baseline: 1.3570x; 1.0172x over previous
#include <cuda_runtime.h>

#define NN 50000
#define NE 800000
#define CIN 128
#define CH 64
#define NB 196  // ceil(NN/256)

// ---------------- scratch (no allocs allowed -> device globals) ----------------
__device__ int   g_cnt[NN];        // in-degree histogram; self-cleaned each call
__device__ int   g_off[NN];        // CSR segment start per node
__device__ int   g_end[NN];        // CSR segment end per node
__device__ int   g_cur[NN];        // reorder cursors
__device__ float g_dis[NN];        // rsqrt(deg+1)
__device__ int   g_src[NE];
__device__ int   g_dst[NE];
__device__ int   g_eidx[NE];       // dst-grouped src indices (CSR adjacency)
__device__ int   g_total;          // atomic base counter (reset by k_probe)
__device__ float g_h1[(size_t)NN * CH];   // dis[i] * (x @ W1)
__device__ float g_acc1[(size_t)NN * CH]; // layer-1 output (post-bias, pre-ReLU)
__device__ float g_h2[(size_t)NN * CH];   // dis[i] * (relu(acc1) @ W2)
__device__ int   g_is64;

// ---------------- probe: index dtype detect + reset base counter ----------------
__global__ void k_probe(const long long* __restrict__ idx) {
    if (threadIdx.x == 0) {
        int ok = 1;
        for (int j = 0; j < 16; j++) {
            long long v = idx[j];
            if (v < 0 || v >= NN) ok = 0;
        }
        g_is64 = ok;
        g_total = 0;
    }
}

// ---------------- convert indices + in-degree histogram ----------------
// g_cnt is all-zero on entry: BSS-zeroed on first call, re-zeroed by k_off after.
__global__ __launch_bounds__(256) void k_deg(const void* __restrict__ idx) {
    int e = blockIdx.x * blockDim.x + threadIdx.x;
    if (e >= NE) return;
    int s, d;
    if (g_is64) {
        const long long* p = (const long long*)idx;
        s = (int)p[e];
        d = (int)p[NE + e];
    } else {
        const int* p = (const int*)idx;
        s = p[e];
        d = p[NE + e];
    }
    g_src[e] = s;
    g_dst[e] = d;
    atomicAdd(&g_cnt[d], 1);
}

// ---------------- fused offsets: block scan + atomic block base ----------------
// Node segments need only be contiguous & disjoint, not id-ordered, so each
// block claims its base via one atomicAdd. Also emits dis and self-cleans g_cnt.
__global__ __launch_bounds__(256) void k_off() {
    __shared__ int sm[256];
    __shared__ int sbase;
    const int t = threadIdx.x;
    int i = blockIdx.x * 256 + t;
    int c = (i < NN) ? g_cnt[i] : 0;
    sm[t] = c;
    __syncthreads();
    for (int o = 1; o < 256; o <<= 1) {
        int u = (t >= o) ? sm[t - o] : 0;
        __syncthreads();
        sm[t] += u;
        __syncthreads();
    }
    if (t == 255) sbase = atomicAdd(&g_total, sm[255]);
    __syncthreads();
    int off = sbase + sm[t] - c;  // block base + in-block exclusive prefix
    if (i < NN) {
        g_off[i] = off;
        g_end[i] = off + c;
        g_cur[i] = off;
        g_dis[i] = rsqrtf((float)(c + 1));  // degree includes self-loop
        g_cnt[i] = 0;                       // clean for next call
    }
}

// ---------------- reorder: pure permutation into dst-grouped adjacency ----------------
__global__ __launch_bounds__(256) void k_reorder() {
    int e = blockIdx.x * blockDim.x + threadIdx.x;
    if (e >= NE) return;
    int d = g_dst[e];
    int pos = atomicAdd(&g_cur[d], 1);
    g_eidx[pos] = g_src[e];
}

// ---------------- packed f32x2 helpers ----------------
__device__ __forceinline__ unsigned long long pack_dup(float v) {
    unsigned long long r;
    asm("mov.b64 %0, {%1, %1};" : "=l"(r) : "r"(__float_as_uint(v)));
    return r;
}
__device__ __forceinline__ void ffma2(unsigned long long& d, unsigned long long a,
                                      unsigned long long b) {
    asm("fma.rn.f32x2 %0, %1, %2, %3;" : "=l"(d) : "l"(a), "l"(b), "l"(d));
}
__device__ __forceinline__ unsigned long long fmul2(unsigned long long a,
                                                    unsigned long long b) {
    unsigned long long r;
    asm("mul.rn.f32x2 %0, %1, %2;" : "=l"(r) : "l"(a), "l"(b));
    return r;
}

// ---------------- GEMM1: h1 = dis[row] * (x @ W1), f32x2 inner loop ----------------
__global__ __launch_bounds__(128) void k_gemm1(const float* __restrict__ x,
                                               const float* __restrict__ W) {
    extern __shared__ float sm[];
    float* Ws = sm;             // 128*64
    float* Xs = sm + CIN * CH;  // 64*130
    const int t = threadIdx.x;
    const int row0 = blockIdx.x * 64;

    {
        const float4* Wg = (const float4*)W;
        float4* Wsv = (float4*)Ws;
        #pragma unroll
        for (int i = 0; i < 16; i++) Wsv[i * 128 + t] = Wg[i * 128 + t];
    }
    #pragma unroll
    for (int i = 0; i < 64; i++) {
        int e = i * 128 + t;
        int r = e >> 7, c = e & 127;
        int gr = row0 + r;
        Xs[r * 130 + c] = (gr < NN) ? __ldg(x + (size_t)gr * CIN + c) : 0.0f;
    }
    __syncthreads();

    const int tx = t & 7;
    const int ty = t >> 3;
    const float* Xp = Xs + ty * 4 * 130;
    const float* Wp = Ws + tx * 8;
    unsigned long long acc[4][4];
    #pragma unroll
    for (int r = 0; r < 4; r++)
        #pragma unroll
        for (int p = 0; p < 4; p++) acc[r][p] = 0ull;  // {0f,0f}

    #pragma unroll 4
    for (int k = 0; k < CIN; k++) {
        ulonglong2 w01 = *(const ulonglong2*)(Wp + k * CH);
        ulonglong2 w23 = *(const ulonglong2*)(Wp + k * CH + 4);
        #pragma unroll
        for (int r = 0; r < 4; r++) {
            unsigned long long xx = pack_dup(Xp[r * 130 + k]);
            ffma2(acc[r][0], xx, w01.x);
            ffma2(acc[r][1], xx, w01.y);
            ffma2(acc[r][2], xx, w23.x);
            ffma2(acc[r][3], xx, w23.y);
        }
    }

    #pragma unroll
    for (int r = 0; r < 4; r++) {
        int gr = row0 + ty * 4 + r;
        if (gr < NN) {
            unsigned long long dd = pack_dup(g_dis[gr]);
            float* hp = g_h1 + (size_t)gr * CH + tx * 8;
            ulonglong2 o01, o23;
            o01.x = fmul2(acc[r][0], dd);
            o01.y = fmul2(acc[r][1], dd);
            o23.x = fmul2(acc[r][2], dd);
            o23.y = fmul2(acc[r][3], dd);
            *(ulonglong2*)hp = o01;
            *(ulonglong2*)(hp + 4) = o23;
        }
    }
}

// ---------------- GEMM2: h2 = dis[row] * (relu(acc1) @ W2), f32x2 ----------------
__global__ __launch_bounds__(128) void k_gemm2(const float* __restrict__ W) {
    __shared__ float Ws[CH * CH];
    __shared__ float Xs[64 * 66];
    const int t = threadIdx.x;
    const int row0 = blockIdx.x * 64;

    {
        const float4* Wg = (const float4*)W;
        float4* Wsv = (float4*)Ws;
        #pragma unroll
        for (int i = 0; i < 8; i++) Wsv[i * 128 + t] = Wg[i * 128 + t];
    }
    #pragma unroll
    for (int i = 0; i < 32; i++) {
        int e = i * 128 + t;
        int r = e >> 6, c = e & 63;
        int gr = row0 + r;
        float v = (gr < NN) ? g_acc1[(size_t)gr * CH + c] : 0.0f;
        Xs[r * 66 + c] = fmaxf(v, 0.0f);  // fused ReLU
    }
    __syncthreads();

    const int tx = t & 7;
    const int ty = t >> 3;
    const float* Xp = Xs + ty * 4 * 66;
    const float* Wp = Ws + tx * 8;
    unsigned long long acc[4][4];
    #pragma unroll
    for (int r = 0; r < 4; r++)
        #pragma unroll
        for (int p = 0; p < 4; p++) acc[r][p] = 0ull;

    #pragma unroll 4
    for (int k = 0; k < CH; k++) {
        ulonglong2 w01 = *(const ulonglong2*)(Wp + k * CH);
        ulonglong2 w23 = *(const ulonglong2*)(Wp + k * CH + 4);
        #pragma unroll
        for (int r = 0; r < 4; r++) {
            unsigned long long xx = pack_dup(Xp[r * 66 + k]);
            ffma2(acc[r][0], xx, w01.x);
            ffma2(acc[r][1], xx, w01.y);
            ffma2(acc[r][2], xx, w23.x);
            ffma2(acc[r][3], xx, w23.y);
        }
    }

    #pragma unroll
    for (int r = 0; r < 4; r++) {
        int gr = row0 + ty * 4 + r;
        if (gr < NN) {
            unsigned long long dd = pack_dup(g_dis[gr]);
            float* hp = g_h2 + (size_t)gr * CH + tx * 8;
            ulonglong2 o01, o23;
            o01.x = fmul2(acc[r][0], dd);
            o01.y = fmul2(acc[r][1], dd);
            o23.x = fmul2(acc[r][2], dd);
            o23.y = fmul2(acc[r][3], dd);
            *(ulonglong2*)hp = o01;
            *(ulonglong2*)(hp + 4) = o23;
        }
    }
}

// ---------------- CSR gather: dst[i] = dis[i]*(hs[i] + sum_e hs[src_e]) + b ----------------
// One warp per node, lane owns 2 columns. 4x unrolled for MLP; destination
// selected in device code (device symbols must never be host-side kernel args).
template <int L>
__global__ __launch_bounds__(256) void k_gather(const float* __restrict__ b,
                                                float* __restrict__ out_arg) {
    const int node = blockIdx.x * 8 + (threadIdx.x >> 5);
    const int lane = threadIdx.x & 31;
    if (node >= NN) return;
    const float* __restrict__ hs = (L == 1) ? g_h1 : g_h2;
    float* __restrict__ dst = (L == 1) ? g_acc1 : out_arg;

    float2 acc = __ldg((const float2*)(hs + (size_t)node * CH) + lane);  // self term

    int e = g_off[node];
    const int s1 = g_end[node];
    for (; e + 4 <= s1; e += 4) {
        int sj0 = __ldg(g_eidx + e);
        int sj1 = __ldg(g_eidx + e + 1);
        int sj2 = __ldg(g_eidx + e + 2);
        int sj3 = __ldg(g_eidx + e + 3);
        float2 v0 = __ldg((const float2*)(hs + (size_t)sj0 * CH) + lane);
        float2 v1 = __ldg((const float2*)(hs + (size_t)sj1 * CH) + lane);
        float2 v2 = __ldg((const float2*)(hs + (size_t)sj2 * CH) + lane);
        float2 v3 = __ldg((const float2*)(hs + (size_t)sj3 * CH) + lane);
        acc.x += v0.x + v1.x + v2.x + v3.x;
        acc.y += v0.y + v1.y + v2.y + v3.y;
    }
    for (; e < s1; e++) {
        int sj = __ldg(g_eidx + e);
        float2 v = __ldg((const float2*)(hs + (size_t)sj * CH) + lane);
        acc.x += v.x;
        acc.y += v.y;
    }

    float ds = g_dis[node];
    float2 bv = __ldg((const float2*)b + lane);
    float2 o;
    o.x = ds * acc.x + bv.x;
    o.y = ds * acc.y + bv.y;
    *((float2*)(dst + (size_t)node * CH) + lane) = o;
}

// ---------------- launch ----------------
extern "C" void kernel_launch(void* const* d_in, const int* in_sizes, int n_in,
                              void* d_out, int out_size) {
    const float* x  = (const float*)d_in[0];
    const void*  ei = d_in[1];
    const float* W1 = (const float*)d_in[2];
    const float* b1 = (const float*)d_in[3];
    const float* W2 = (const float*)d_in[4];
    const float* b2 = (const float*)d_in[5];
    float* out = (float*)d_out;

    const int gemm1_smem = (CIN * CH + 64 * 130) * (int)sizeof(float);
    cudaFuncSetAttribute(k_gemm1, cudaFuncAttributeMaxDynamicSharedMemorySize,
                         gemm1_smem);

    k_probe<<<1, 32>>>((const long long*)ei);
    k_deg<<<NE / 256, 256>>>(ei);
    k_off<<<NB, 256>>>();
    k_reorder<<<NE / 256, 256>>>();
    k_gemm1<<<(NN + 63) / 64, 128, gemm1_smem>>>(x, W1);
    k_gather<1><<<(NN + 7) / 8, 256>>>(b1, nullptr);
    k_gemm2<<<(NN + 63) / 64, 128>>>(W2);
    k_gather<2><<<(NN + 7) / 8, 256>>>(b2, out);
}